// round 3
// baseline (speedup 1.0000x reference)
#include <cuda_runtime.h>
#include <cuda_bf16.h>

// BentPrototypeQuantizer: codebook == all 64 vertices of {-1,+1}^6 (proved R0,
// rel_err=0.0 confirmed). Nearest vertex separable: q_d = (x_d>0)?+1:-1
// (tie at exactly 0.0 -> -1, matching np reference; keep the compare form,
// NOT the sign-bit trick, to preserve that tie).
//
// R3: exact-tile unpredicated fast path (n4 divisible by TILE), ITEMS=8
// front-batched loads per thread (MLP=8), generic predicated kernel only as
// fallback for non-divisible sizes.

#define THREADS 256
#define ITEMS 8
#define TILE (THREADS * ITEMS)

__global__ void __launch_bounds__(THREADS)
bent_quantize_exact(const float4* __restrict__ x, float4* __restrict__ out) {
    const float4* xp = x + (size_t)blockIdx.x * TILE + threadIdx.x;
    float4* op = out + (size_t)blockIdx.x * TILE + threadIdx.x;

    float4 v[ITEMS];
    #pragma unroll
    for (int k = 0; k < ITEMS; k++) v[k] = xp[k * THREADS];

    #pragma unroll
    for (int k = 0; k < ITEMS; k++) {
        float4 o;
        o.x = (v[k].x > 0.0f) ? 1.0f : -1.0f;
        o.y = (v[k].y > 0.0f) ? 1.0f : -1.0f;
        o.z = (v[k].z > 0.0f) ? 1.0f : -1.0f;
        o.w = (v[k].w > 0.0f) ? 1.0f : -1.0f;
        op[k * THREADS] = o;
    }
}

// Generic fallback: any element count, scalar.
__global__ void __launch_bounds__(THREADS)
bent_quantize_generic(const float* __restrict__ x, float* __restrict__ out, int n) {
    int i = blockIdx.x * blockDim.x + threadIdx.x;
    int stride = gridDim.x * blockDim.x;
    for (; i < n; i += stride) {
        float v = x[i];
        out[i] = (v > 0.0f) ? 1.0f : -1.0f;
    }
}

extern "C" void kernel_launch(void* const* d_in, const int* in_sizes, int n_in,
                              void* d_out, int out_size) {
    const float* x = (const float*)d_in[0];
    float* out = (float*)d_out;
    int n = in_sizes[0];

    if ((n & 3) == 0 && ((n >> 2) % TILE) == 0) {
        int n4 = n >> 2;
        int blocks = n4 / TILE;   // 1572864 / 2048 = 768 for the bench shape
        bent_quantize_exact<<<blocks, THREADS>>>((const float4*)x, (float4*)out);
    } else {
        int blocks = (n + THREADS - 1) / THREADS;
        if (blocks > 8192) blocks = 8192;
        if (blocks < 1) blocks = 1;
        bent_quantize_generic<<<blocks, THREADS>>>(x, out, n);
    }
}